// round 14
// baseline (speedup 1.0000x reference)
#include <cuda_runtime.h>
#include <cuda_bf16.h>
#include <stdint.h>

#define BATCH 65536
#define VOCAB 1048576
#define QMAX 32600.0f

// ---------------- device scratch (no allocation allowed) ----------------
__device__ __align__(16) int8_t g_Da1[BATCH * 1024];
__device__ __align__(16) int8_t g_Da0[BATCH * 1024];
__device__ __align__(16) int8_t g_Db1[BATCH * 1024];
__device__ __align__(16) int8_t g_Db0[BATCH * 1024];
__device__ float g_F[BATCH * 1024];          // fp32 activation staging
__device__ float g_sa[BATCH];
__device__ float g_sb[BATCH];
__device__ __align__(16) int8_t g_wd1[2424832];
__device__ __align__(16) int8_t g_wd0[2424832];
__device__ float g_ws[3712];

// weight digit offsets (transposed [N,K], Kpad mult of 64):
#define OFF_BW0 0        // [512 ,  64]
#define OFF_BW1 32768    // [256 , 512]
#define OFF_BW2 163840   // [128 , 256]
#define OFF_TW0 196608   // [1024, 512]
#define OFF_TW1 720896   // [1024,1024]
#define OFF_TW2 1769472  // [512 ,1024]
#define OFF_TW3 2293760  // [256 , 512]   total 2424832
// weight scale offsets (per N-row):
#define SOF_BW0 0
#define SOF_BW1 512
#define SOF_BW2 768
#define SOF_TW0 896
#define SOF_TW1 1920
#define SOF_TW2 2944
#define SOF_TW3 3456

__device__ __forceinline__ void f2hilo(float x, uint16_t &hi, uint16_t &lo) {
    __nv_bfloat16 h = __float2bfloat16(x);
    float hf = __bfloat162float(h);
    __nv_bfloat16 l = __float2bfloat16(x - hf);
    hi = __bfloat16_as_ushort(h);
    lo = __bfloat16_as_ushort(l);
}
__device__ __forceinline__ void q2d(float v, float inv, int8_t &d1, int8_t &d0) {
    int i = __float2int_rn(v * inv);
    int t1 = (i + 128) >> 8;
    d1 = (int8_t)t1;
    d0 = (int8_t)(i - (t1 << 8));
}

// ---------------- PTX helpers ----------------
__device__ __forceinline__ uint32_t smem_u32(const void* p) {
    return (uint32_t)__cvta_generic_to_shared(p);
}
__device__ __forceinline__ void cp16(uint32_t s, const void* g) {
    asm volatile("cp.async.cg.shared.global [%0], [%1], 16;\n" :: "r"(s), "l"(g));
}
#define CP_COMMIT() asm volatile("cp.async.commit_group;\n" ::: "memory")
#define CP_WAIT0()  asm volatile("cp.async.wait_group 0;\n" ::: "memory")
#define CP_WAIT1()  asm volatile("cp.async.wait_group 1;\n" ::: "memory")

__device__ __forceinline__ void mma_s8(int* c, const uint32_t* a, const uint32_t* b) {
    asm volatile(
        "mma.sync.aligned.m16n8k32.row.col.s32.s8.s8.s32 "
        "{%0,%1,%2,%3}, {%4,%5,%6,%7}, {%8,%9}, {%0,%1,%2,%3};\n"
        : "+r"(c[0]), "+r"(c[1]), "+r"(c[2]), "+r"(c[3])
        : "r"(a[0]), "r"(a[1]), "r"(a[2]), "r"(a[3]), "r"(b[0]), "r"(b[1]));
}
__device__ __forceinline__ void mma_bf16(float* c, const uint32_t* a, const uint32_t* b) {
    asm volatile(
        "mma.sync.aligned.m16n8k16.row.col.f32.bf16.bf16.f32 "
        "{%0,%1,%2,%3}, {%4,%5,%6,%7}, {%8,%9}, {%0,%1,%2,%3};\n"
        : "+f"(c[0]), "+f"(c[1]), "+f"(c[2]), "+f"(c[3])
        : "r"(a[0]), "r"(a[1]), "r"(a[2]), "r"(a[3]), "r"(b[0]), "r"(b[1]));
}
__device__ __forceinline__ void ldsm4(uint32_t* r, uint32_t addr) {
    asm volatile("ldmatrix.sync.aligned.m8n8.x4.shared.b16 {%0,%1,%2,%3}, [%4];\n"
                 : "=r"(r[0]), "=r"(r[1]), "=r"(r[2]), "=r"(r[3])
                 : "r"(addr));
}
// SW64 swizzle for 64-byte rows
__device__ __forceinline__ uint32_t swz(uint32_t off) {
    return off ^ ((off >> 3) & 0x30);
}

// ---------------- weight transpose (fp32 out, coalesced) ----------------
__global__ void transpose_w(const float* __restrict__ W, float* __restrict__ out,
                            int K, int N, int Kpad) {
    __shared__ float tile[32][65];
    const int tx = threadIdx.x & 31;
    const int ty = threadIdx.x >> 5;
    const int n0 = blockIdx.x * 32;
    const int k0 = blockIdx.y * 64;

#pragma unroll
    for (int kk = ty; kk < 64; kk += 8) {
        int k = k0 + kk, n = n0 + tx;
        tile[tx][kk] = (k < K) ? W[(size_t)k * N + n] : 0.f;
    }
    __syncthreads();
#pragma unroll
    for (int r = ty; r < 32; r += 8) {
        int n = n0 + r;
        int k = k0 + tx * 2;
        *(float2*)&out[(size_t)n * Kpad + k] = make_float2(tile[r][tx * 2], tile[r][tx * 2 + 1]);
    }
}

// ---------------- per-row quantize fp32 -> digit pair planes + scale ---------
__global__ void quant_rows(const float* __restrict__ src, int8_t* __restrict__ d1,
                           int8_t* __restrict__ d0, float* __restrict__ sc, int rowlen) {
    const int warp = threadIdx.x >> 5, lane = threadIdx.x & 31;
    const size_t r = (size_t)blockIdx.x * 8 + warp;
    const float* row = src + r * rowlen;
    float4 v[8];
    float mx = 0.f;
#pragma unroll
    for (int i = 0; i < 8; i++) {
        int k = i * 128 + lane * 4;
        if (k < rowlen) {
            v[i] = *(const float4*)(row + k);
            mx = fmaxf(mx, fmaxf(fmaxf(fabsf(v[i].x), fabsf(v[i].y)),
                                 fmaxf(fabsf(v[i].z), fabsf(v[i].w))));
        }
    }
#pragma unroll
    for (int o = 16; o; o >>= 1) mx = fmaxf(mx, __shfl_xor_sync(0xFFFFFFFFu, mx, o));
    const float inv = QMAX / fmaxf(mx, 1e-20f);
    if (lane == 0) sc[r] = mx / QMAX;
#pragma unroll
    for (int i = 0; i < 8; i++) {
        int k = i * 128 + lane * 4;
        if (k < rowlen) {
            char4 c1, c0;
            int8_t a, b;
            q2d(v[i].x, inv, a, b); c1.x = a; c0.x = b;
            q2d(v[i].y, inv, a, b); c1.y = a; c0.y = b;
            q2d(v[i].z, inv, a, b); c1.z = a; c0.z = b;
            q2d(v[i].w, inv, a, b); c1.w = a; c0.w = b;
            *(char4*)(d1 + r * rowlen + k) = c1;
            *(char4*)(d0 + r * rowlen + k) = c0;
        }
    }
}

// ---------------- dense input -> digits (Kpad 64) ----------------
__global__ void conv_dense_q(const float* __restrict__ dense, int8_t* __restrict__ d1,
                             int8_t* __restrict__ d0, float* __restrict__ sc) {
    const int warp = threadIdx.x >> 5, lane = threadIdx.x & 31;
    const size_t s = (size_t)blockIdx.x * 8 + warp;
    float v = (lane < 13) ? dense[s * 13 + lane] : 0.f;
    float mx = fabsf(v);
#pragma unroll
    for (int o = 16; o; o >>= 1) mx = fmaxf(mx, __shfl_xor_sync(0xFFFFFFFFu, mx, o));
    const float inv = QMAX / fmaxf(mx, 1e-20f);
    if (lane == 0) sc[s] = mx / QMAX;
    int c0 = 2 * lane, c1 = c0 + 1;
    float f0 = (c0 < 13) ? dense[s * 13 + c0] : 0.f;
    float f1 = (c1 < 13) ? dense[s * 13 + c1] : 0.f;
    int8_t a1, a0, b1, b0;
    q2d(f0, inv, a1, a0);
    q2d(f1, inv, b1, b0);
    char2 p1; p1.x = a1; p1.y = b1;
    char2 p0; p0.x = a0; p0.y = b0;
    *(char2*)(d1 + s * 64 + c0) = p1;
    *(char2*)(d0 + s * 64 + c0) = p0;
}

// ---------------- int8 double-digit GEMM: F = act(A @ W^T + b) ---------------
// Block 128x64, warp 32x32 (4m x 2n warps), K-chunk 64, 3-stage, 2 CTA/SM.
#define QSTAGE  24576        // A1 8K | A0 8K | B1 4K | B0 4K
#define QOFF_A0 8192
#define QOFF_B1 16384
#define QOFF_B0 20480

__global__ __launch_bounds__(256, 2)
void gemm_imma(const int8_t* __restrict__ A1, const int8_t* __restrict__ A0,
               const float* __restrict__ sA,
               const int8_t* __restrict__ W1, const int8_t* __restrict__ W0,
               const float* __restrict__ sW,
               const float* __restrict__ bias, float* __restrict__ Fout,
               int Nsz, int K, int relu) {
    extern __shared__ __align__(16) uint8_t dsm[];
    const uint32_t sbase = smem_u32(dsm);

    const int tid  = threadIdx.x;
    const int lane = tid & 31;
    const int warp = tid >> 5;
    const int wm = warp & 3;           // m offset 32 each
    const int wn = warp >> 2;          // n offset 32 each
    const size_t mBase = (size_t)blockIdx.y * 128;
    const int    nBase = blockIdx.x * 64;
    const int    nch   = K >> 6;

    const int r0 = tid >> 2, ch = tid & 3;
    const int8_t* gA1 = A1 + (mBase + r0) * (size_t)K + ch * 16;
    const int8_t* gA0 = A0 + (mBase + r0) * (size_t)K + ch * 16;
    const int8_t* gB1 = W1 + (size_t)(nBase + r0) * K + ch * 16;
    const int8_t* gB0 = W0 + (size_t)(nBase + r0) * K + ch * 16;
    const uint32_t soff = swz((uint32_t)r0 * 64 + ch * 16);
    const size_t rowD = (size_t)64 * K;

    auto issue = [&](int c) {
        const uint32_t st = sbase + (c % 3) * QSTAGE + soff;
        const int k0 = c << 6;
        cp16(st,                   gA1 + k0);
        cp16(st + 4096,            gA1 + rowD + k0);
        cp16(st + QOFF_A0,         gA0 + k0);
        cp16(st + QOFF_A0 + 4096,  gA0 + rowD + k0);
        cp16(st + QOFF_B1,         gB1 + k0);
        cp16(st + QOFF_B0,         gB0 + k0);
    };

    int acchi[2][4][4], accmid[2][4][4];
#pragma unroll
    for (int a = 0; a < 2; a++)
#pragma unroll
        for (int b = 0; b < 4; b++)
#pragma unroll
            for (int c = 0; c < 4; c++) { acchi[a][b][c] = 0; accmid[a][b][c] = 0; }

    const uint32_t aRow = (uint32_t)(wm * 32 + (lane & 15)) * 64 + (lane >> 4) * 16;
    const uint32_t bRow = (uint32_t)(wn * 32 + (lane & 7) + ((lane >> 4) << 3)) * 64
                        + (((lane >> 3) & 1) << 4);

    issue(0); CP_COMMIT();
    if (nch > 1) { issue(1); CP_COMMIT(); }

    for (int c = 0; c < nch; c++) {
        if (c + 1 < nch) CP_WAIT1(); else CP_WAIT0();
        __syncthreads();
        if (c + 2 < nch) { issue(c + 2); CP_COMMIT(); }

        const uint32_t st = sbase + (c % 3) * QSTAGE;
#pragma unroll
        for (int kk = 0; kk < 2; kk++) {
            uint32_t a1[2][4], a0[2][4], b1[2][4], b0[2][4];
#pragma unroll
            for (int mt = 0; mt < 2; mt++) {
                uint32_t off = swz(aRow + mt * 16 * 64 + kk * 32);
                ldsm4(a1[mt], st + off);
                ldsm4(a0[mt], st + QOFF_A0 + off);
            }
#pragma unroll
            for (int np = 0; np < 2; np++) {
                uint32_t off = swz(bRow + np * 16 * 64 + kk * 32);
                ldsm4(b1[np], st + QOFF_B1 + off);
                ldsm4(b0[np], st + QOFF_B0 + off);
            }
            // pass hi: d1a x d1b
#pragma unroll
            for (int f = 0; f < 4; f++)
#pragma unroll
                for (int mt = 0; mt < 2; mt++)
                    mma_s8(acchi[mt][f], a1[mt], &b1[f >> 1][(f & 1) * 2]);
            // pass mid1: d1a x d0b
#pragma unroll
            for (int f = 0; f < 4; f++)
#pragma unroll
                for (int mt = 0; mt < 2; mt++)
                    mma_s8(accmid[mt][f], a1[mt], &b0[f >> 1][(f & 1) * 2]);
            // pass mid2: d0a x d1b
#pragma unroll
            for (int f = 0; f < 4; f++)
#pragma unroll
                for (int mt = 0; mt < 2; mt++)
                    mma_s8(accmid[mt][f], a0[mt], &b1[f >> 1][(f & 1) * 2]);
        }
    }

    // epilogue: v = sA[m]*sW[n]*(65536*hi + 256*mid) + bias
#pragma unroll
    for (int mt = 0; mt < 2; mt++) {
        size_t m0 = mBase + wm * 32 + mt * 16 + (lane >> 2);
        float sm0 = sA[m0], sm1 = sA[m0 + 8];
#pragma unroll
        for (int f = 0; f < 4; f++) {
            int n = nBase + wn * 32 + f * 8 + (lane & 3) * 2;
            float w0 = sW[n], w1 = sW[n + 1];
            float b0 = bias[n], b1 = bias[n + 1];
            float v0 = (65536.f * (float)acchi[mt][f][0] + 256.f * (float)accmid[mt][f][0]) * sm0 * w0 + b0;
            float v1 = (65536.f * (float)acchi[mt][f][1] + 256.f * (float)accmid[mt][f][1]) * sm0 * w1 + b1;
            float v2 = (65536.f * (float)acchi[mt][f][2] + 256.f * (float)accmid[mt][f][2]) * sm1 * w0 + b0;
            float v3 = (65536.f * (float)acchi[mt][f][3] + 256.f * (float)accmid[mt][f][3]) * sm1 * w1 + b1;
            if (relu) {
                v0 = fmaxf(v0, 0.f); v1 = fmaxf(v1, 0.f);
                v2 = fmaxf(v2, 0.f); v3 = fmaxf(v3, 0.f);
            }
            *(float2*)&Fout[m0 * Nsz + n]       = make_float2(v0, v1);
            *(float2*)&Fout[(m0 + 8) * Nsz + n] = make_float2(v2, v3);
        }
    }
}

// ---------------- interaction: HMMA gram (bf16x3) + row quantize -------------
#define ISTRIDE 272
#define IPLANE  8704
#define ISAMP   17408

__global__ __launch_bounds__(256, 1)
void interact_kernel(const float* __restrict__ H, const float* __restrict__ emb,
                     const int* __restrict__ sidx,
                     int8_t* __restrict__ Od1, int8_t* __restrict__ Od0,
                     float* __restrict__ sc) {
    extern __shared__ __align__(16) uint8_t ism[];
    const int warp = threadIdx.x >> 5;
    const int lane = threadIdx.x & 31;
    const size_t smp = (size_t)blockIdx.x * 8 + warp;
    uint8_t* my = ism + warp * ISAMP;
    const uint32_t base = smem_u32(my);

    int idx26[26];
#pragma unroll
    for (int v = 0; v < 26; v++) idx26[v] = sidx[smp * 26 + v] & (VOCAB - 1);

    // row 0 = h (fp32 from F), split to bf16 hi/lo planes; keep fp32 in regs
    float hv[4];
    {
        float4 h4 = *(const float4*)&H[smp * 128 + lane * 4];
        hv[0] = h4.x; hv[1] = h4.y; hv[2] = h4.z; hv[3] = h4.w;
        uint16_t hh[4], ll[4];
#pragma unroll
        for (int j = 0; j < 4; j++) f2hilo(hv[j], hh[j], ll[j]);
        *(uint2*)(my + lane * 8) =
            make_uint2((uint32_t)hh[0] | ((uint32_t)hh[1] << 16),
                       (uint32_t)hh[2] | ((uint32_t)hh[3] << 16));
        *(uint2*)(my + IPLANE + lane * 8) =
            make_uint2((uint32_t)ll[0] | ((uint32_t)ll[1] << 16),
                       (uint32_t)ll[2] | ((uint32_t)ll[3] << 16));
    }
#pragma unroll
    for (int r = 27; r < 32; r++) {
        *(uint2*)(my + r * ISTRIDE + lane * 8) = make_uint2(0, 0);
        *(uint2*)(my + IPLANE + r * ISTRIDE + lane * 8) = make_uint2(0, 0);
    }

#pragma unroll
    for (int w0 = 0; w0 < 26; w0 += 8) {
        float4 e[8];
        const int cnt = (26 - w0 < 8) ? (26 - w0) : 8;
#pragma unroll
        for (int j = 0; j < 8; j++)
            if (j < cnt)
                e[j] = *(const float4*)&emb[(size_t)idx26[w0 + j] * 128 + lane * 4];
#pragma unroll
        for (int j = 0; j < 8; j++)
            if (j < cnt) {
                const int r = w0 + j + 1;
                float f[4] = {e[j].x, e[j].y, e[j].z, e[j].w};
                uint16_t h[4], l[4];
#pragma unroll
                for (int q = 0; q < 4; q++) f2hilo(f[q], h[q], l[q]);
                *(uint2*)(my + r * ISTRIDE + lane * 8) =
                    make_uint2((uint32_t)h[0] | ((uint32_t)h[1] << 16),
                               (uint32_t)h[2] | ((uint32_t)h[3] << 16));
                *(uint2*)(my + IPLANE + r * ISTRIDE + lane * 8) =
                    make_uint2((uint32_t)l[0] | ((uint32_t)l[1] << 16),
                               (uint32_t)l[2] | ((uint32_t)l[3] << 16));
            }
    }
    __syncwarp();

    float acc[2][4][4];
#pragma unroll
    for (int a = 0; a < 2; a++)
#pragma unroll
        for (int b = 0; b < 4; b++)
#pragma unroll
            for (int c = 0; c < 4; c++) acc[a][b][c] = 0.f;

    const uint32_t aoff = base + (uint32_t)(lane & 15) * ISTRIDE + (lane >> 4) * 16;
    const uint32_t boff = base + (uint32_t)((lane & 7) + ((lane >> 4) << 3)) * ISTRIDE
                        + (((lane >> 3) & 1) << 4);

#pragma unroll
    for (int ks = 0; ks < 8; ks++) {
        const uint32_t kb = ks * 32;
        uint32_t aH[2][4], aL[2][4], bB[2][4];
        ldsm4(aH[0], aoff + kb);
        ldsm4(aH[1], aoff + 16 * ISTRIDE + kb);
        ldsm4(aL[0], aoff + IPLANE + kb);
        ldsm4(aL[1], aoff + IPLANE + 16 * ISTRIDE + kb);
        ldsm4(bB[0], boff + kb);
        ldsm4(bB[1], boff + 16 * ISTRIDE + kb);
#pragma unroll
        for (int g = 0; g < 2; g++)
#pragma unroll
            for (int mt = 0; mt < 2; mt++) {
                mma_bf16(acc[mt][g * 2],     aH[mt], &bB[g][0]);
                mma_bf16(acc[mt][g * 2 + 1], aH[mt], &bB[g][2]);
            }
#pragma unroll
        for (int g = 0; g < 2; g++) {
#pragma unroll
            for (int mt = 0; mt < 2; mt++) {
                mma_bf16(acc[mt][g * 2],     aL[mt], &bB[g][0]);
                mma_bf16(acc[mt][g * 2 + 1], aL[mt], &bB[g][2]);
            }
            ldsm4(bB[g], boff + IPLANE + g * 16 * ISTRIDE + kb);
        }
#pragma unroll
        for (int g = 0; g < 2; g++)
#pragma unroll
            for (int mt = 0; mt < 2; mt++) {
                mma_bf16(acc[mt][g * 2],     aH[mt], &bB[g][0]);
                mma_bf16(acc[mt][g * 2 + 1], aH[mt], &bB[g][2]);
            }
    }

    // row max over h + gram values
    float mx = fmaxf(fmaxf(fabsf(hv[0]), fabsf(hv[1])), fmaxf(fabsf(hv[2]), fabsf(hv[3])));
#pragma unroll
    for (int mt = 0; mt < 2; mt++)
#pragma unroll
        for (int nt = 0; nt < 4; nt++)
#pragma unroll
            for (int q = 0; q < 4; q++) mx = fmaxf(mx, fabsf(acc[mt][nt][q]));
#pragma unroll
    for (int o = 16; o; o >>= 1) mx = fmaxf(mx, __shfl_xor_sync(0xFFFFFFFFu, mx, o));
    const float inv = QMAX / fmaxf(mx, 1e-20f);
    if (lane == 0) sc[smp] = mx / QMAX;

    // h digits, cols [0,128)
    {
        char4 c1, c0;
        int8_t a, b;
        q2d(hv[0], inv, a, b); c1.x = a; c0.x = b;
        q2d(hv[1], inv, a, b); c1.y = a; c0.y = b;
        q2d(hv[2], inv, a, b); c1.z = a; c0.z = b;
        q2d(hv[3], inv, a, b); c1.w = a; c0.w = b;
        *(char4*)(Od1 + smp * 512 + lane * 4) = c1;
        *(char4*)(Od0 + smp * 512 + lane * 4) = c0;
    }
    // triu digits, cols [128, 506)
#pragma unroll
    for (int mt = 0; mt < 2; mt++)
#pragma unroll
        for (int nt = 0; nt < 4; nt++)
#pragma unroll
            for (int q = 0; q < 4; q++) {
                int i = mt * 16 + (lane >> 2) + ((q >> 1) << 3);
                int j = nt * 8 + (lane & 3) * 2 + (q & 1);
                if (i <= j && j < 27) {
                    int flat = 27 * i - (i * (i - 1)) / 2 + (j - i);
                    int8_t a, b;
                    q2d(acc[mt][nt][q], inv, a, b);
                    Od1[smp * 512 + 128 + flat] = a;
                    Od0[smp * 512 + 128 + flat] = b;
                }
            }
    if (lane < 6) {
        Od1[smp * 512 + 506 + lane] = 0;
        Od0[smp * 512 + 506 + lane] = 0;
    }
}

// ---------------- final 256 -> 1 dot (fp32 in) ----------------
__global__ void final_dot_kernel(const float* __restrict__ F, const float* __restrict__ w,
                                 const float* __restrict__ b, float* __restrict__ out) {
    const int warp = threadIdx.x >> 5;
    const int lane = threadIdx.x & 31;
    const size_t s = (size_t)blockIdx.x * 8 + warp;
    float acc = 0.f;
#pragma unroll
    for (int q = 0; q < 2; q++) {
        float4 x = *(const float4*)&F[s * 256 + lane * 8 + q * 4];
        acc += x.x * w[lane * 8 + q * 4]     + x.y * w[lane * 8 + q * 4 + 1]
             + x.z * w[lane * 8 + q * 4 + 2] + x.w * w[lane * 8 + q * 4 + 3];
    }
#pragma unroll
    for (int o = 16; o; o >>= 1) acc += __shfl_xor_sync(0xFFFFFFFFu, acc, o);
    if (lane == 0) out[s] = acc + b[0];
}

// ---------------- host launch ----------------
extern "C" void kernel_launch(void* const* d_in, const int* in_sizes, int n_in,
                              void* d_out, int out_size) {
    const float* dense = (const float*)d_in[0];
    const int*   sidx  = (const int*)d_in[1];
    const float* emb   = (const float*)d_in[2];
    const float* bw0 = (const float*)d_in[3];  const float* bb0 = (const float*)d_in[4];
    const float* bw1 = (const float*)d_in[5];  const float* bb1 = (const float*)d_in[6];
    const float* bw2 = (const float*)d_in[7];  const float* bb2 = (const float*)d_in[8];
    const float* tw0 = (const float*)d_in[9];  const float* tb0 = (const float*)d_in[10];
    const float* tw1 = (const float*)d_in[11]; const float* tb1 = (const float*)d_in[12];
    const float* tw2 = (const float*)d_in[13]; const float* tb2 = (const float*)d_in[14];
    const float* tw3 = (const float*)d_in[15]; const float* tb3 = (const float*)d_in[16];
    const float* tw4 = (const float*)d_in[17]; const float* tb4 = (const float*)d_in[18];

    int8_t *Da1, *Da0, *Db1, *Db0, *wd1, *wd0;
    float *F, *sa, *sb, *ws;
    cudaGetSymbolAddress((void**)&Da1, g_Da1);
    cudaGetSymbolAddress((void**)&Da0, g_Da0);
    cudaGetSymbolAddress((void**)&Db1, g_Db1);
    cudaGetSymbolAddress((void**)&Db0, g_Db0);
    cudaGetSymbolAddress((void**)&F,   g_F);
    cudaGetSymbolAddress((void**)&sa,  g_sa);
    cudaGetSymbolAddress((void**)&sb,  g_sb);
    cudaGetSymbolAddress((void**)&wd1, g_wd1);
    cudaGetSymbolAddress((void**)&wd0, g_wd0);
    cudaGetSymbolAddress((void**)&ws,  g_ws);

    const int DSM = 3 * QSTAGE;        // 73728
    const int ISM = 8 * ISAMP;         // 139264
    cudaFuncSetAttribute(gemm_imma, cudaFuncAttributeMaxDynamicSharedMemorySize, DSM);
    cudaFuncSetAttribute(interact_kernel, cudaFuncAttributeMaxDynamicSharedMemorySize, ISM);

    dim3 blk(256);

    // weight transpose (fp32 into F regions), then per-row digit quantization
    transpose_w<<<dim3(16, 1),   blk>>>(bw0, F + OFF_BW0, 13,   512,  64);
    transpose_w<<<dim3(8, 8),    blk>>>(bw1, F + OFF_BW1, 512,  256,  512);
    transpose_w<<<dim3(4, 4),    blk>>>(bw2, F + OFF_BW2, 256,  128,  256);
    transpose_w<<<dim3(32, 8),   blk>>>(tw0, F + OFF_TW0, 506,  1024, 512);
    transpose_w<<<dim3(32, 16),  blk>>>(tw1, F + OFF_TW1, 1024, 1024, 1024);
    transpose_w<<<dim3(16, 16),  blk>>>(tw2, F + OFF_TW2, 1024, 512,  1024);
    transpose_w<<<dim3(8, 8),    blk>>>(tw3, F + OFF_TW3, 512,  256,  512);

    quant_rows<<<64,  blk>>>(F + OFF_BW0, wd1 + OFF_BW0, wd0 + OFF_BW0, ws + SOF_BW0, 64);
    quant_rows<<<32,  blk>>>(F + OFF_BW1, wd1 + OFF_BW1, wd0 + OFF_BW1, ws + SOF_BW1, 512);
    quant_rows<<<16,  blk>>>(F + OFF_BW2, wd1 + OFF_BW2, wd0 + OFF_BW2, ws + SOF_BW2, 256);
    quant_rows<<<128, blk>>>(F + OFF_TW0, wd1 + OFF_TW0, wd0 + OFF_TW0, ws + SOF_TW0, 512);
    quant_rows<<<128, blk>>>(F + OFF_TW1, wd1 + OFF_TW1, wd0 + OFF_TW1, ws + SOF_TW1, 1024);
    quant_rows<<<64,  blk>>>(F + OFF_TW2, wd1 + OFF_TW2, wd0 + OFF_TW2, ws + SOF_TW2, 1024);
    quant_rows<<<32,  blk>>>(F + OFF_TW3, wd1 + OFF_TW3, wd0 + OFF_TW3, ws + SOF_TW3, 512);

    // dense input -> digits
    conv_dense_q<<<BATCH / 8, blk>>>(dense, Da1, Da0, sa);

    // bottom MLP
    gemm_imma<<<dim3(8, 512), blk, DSM>>>(Da1, Da0, sa, wd1 + OFF_BW0, wd0 + OFF_BW0, ws + SOF_BW0, bb0, F, 512, 64, 1);
    quant_rows<<<BATCH / 8, blk>>>(F, Db1, Db0, sb, 512);
    gemm_imma<<<dim3(4, 512), blk, DSM>>>(Db1, Db0, sb, wd1 + OFF_BW1, wd0 + OFF_BW1, ws + SOF_BW1, bb1, F, 256, 512, 1);
    quant_rows<<<BATCH / 8, blk>>>(F, Da1, Da0, sa, 256);
    gemm_imma<<<dim3(2, 512), blk, DSM>>>(Da1, Da0, sa, wd1 + OFF_BW2, wd0 + OFF_BW2, ws + SOF_BW2, bb2, F, 128, 256, 1);

    // gather + interaction -> digits [B,512] + scale
    interact_kernel<<<BATCH / 8, blk, ISM>>>(F, emb, sidx, Db1, Db0, sb);

    // top MLP
    gemm_imma<<<dim3(16, 512), blk, DSM>>>(Db1, Db0, sb, wd1 + OFF_TW0, wd0 + OFF_TW0, ws + SOF_TW0, tb0, F, 1024, 512, 1);
    quant_rows<<<BATCH / 8, blk>>>(F, Da1, Da0, sa, 1024);
    gemm_imma<<<dim3(16, 512), blk, DSM>>>(Da1, Da0, sa, wd1 + OFF_TW1, wd0 + OFF_TW1, ws + SOF_TW1, tb1, F, 1024, 1024, 1);
    quant_rows<<<BATCH / 8, blk>>>(F, Db1, Db0, sb, 1024);
    gemm_imma<<<dim3(8, 512), blk, DSM>>>(Db1, Db0, sb, wd1 + OFF_TW2, wd0 + OFF_TW2, ws + SOF_TW2, tb2, F, 512, 1024, 1);
    quant_rows<<<BATCH / 8, blk>>>(F, Da1, Da0, sa, 512);
    gemm_imma<<<dim3(4, 512), blk, DSM>>>(Da1, Da0, sa, wd1 + OFF_TW3, wd0 + OFF_TW3, ws + SOF_TW3, tb3, F, 256, 512, 1);

    // final 256 -> 1
    final_dot_kernel<<<BATCH / 8, blk>>>(F, tw4, tb4, (float*)d_out);
}

// round 15
// speedup vs baseline: 1.7548x; 1.7548x over previous
#include <cuda_runtime.h>
#include <cuda_bf16.h>
#include <stdint.h>

#define BATCH 65536
#define VOCAB 1048576

// ---------------- device scratch (no allocation allowed) ----------------
__device__ uint16_t g_bufA_hi[BATCH * 1024];
__device__ uint16_t g_bufA_lo[BATCH * 1024];
__device__ uint16_t g_bufB_hi[BATCH * 1024];
__device__ uint16_t g_bufB_lo[BATCH * 1024];
__device__ uint16_t g_wt_hi[2408448];
__device__ uint16_t g_wt_lo[2408448];

// weight offsets (transposed [N,K], K padded to mult of 32):
#define OFF_BW0 0        // [512 ,  32]
#define OFF_BW1 16384    // [256 , 512]
#define OFF_BW2 147456   // [128 , 256]
#define OFF_TW0 180224   // [1024, 512]
#define OFF_TW1 704512   // [1024,1024]
#define OFF_TW2 1753088  // [512 ,1024]
#define OFF_TW3 2277376  // [256 , 512]   total 2408448

__device__ __forceinline__ void f2hilo(float x, uint16_t &hi, uint16_t &lo) {
    __nv_bfloat16 h = __float2bfloat16(x);
    float hf = __bfloat162float(h);
    __nv_bfloat16 l = __float2bfloat16(x - hf);
    hi = __bfloat16_as_ushort(h);
    lo = __bfloat16_as_ushort(l);
}
__device__ __forceinline__ float b2f(uint16_t u) {
    return __bfloat162float(__ushort_as_bfloat16(u));
}

// ---------------- PTX helpers ----------------
__device__ __forceinline__ uint32_t smem_u32(const void* p) {
    return (uint32_t)__cvta_generic_to_shared(p);
}
__device__ __forceinline__ void cp16(uint32_t s, const void* g) {
    asm volatile("cp.async.cg.shared.global [%0], [%1], 16;\n" :: "r"(s), "l"(g));
}
#define CP_COMMIT() asm volatile("cp.async.commit_group;\n" ::: "memory")
#define CP_WAIT0()  asm volatile("cp.async.wait_group 0;\n" ::: "memory")
#define CP_WAIT1()  asm volatile("cp.async.wait_group 1;\n" ::: "memory")

__device__ __forceinline__ void mma_bf16(float* c, const uint32_t* a, const uint32_t* b) {
    asm volatile(
        "mma.sync.aligned.m16n8k16.row.col.f32.bf16.bf16.f32 "
        "{%0,%1,%2,%3}, {%4,%5,%6,%7}, {%8,%9}, {%0,%1,%2,%3};\n"
        : "+f"(c[0]), "+f"(c[1]), "+f"(c[2]), "+f"(c[3])
        : "r"(a[0]), "r"(a[1]), "r"(a[2]), "r"(a[3]), "r"(b[0]), "r"(b[1]));
}
__device__ __forceinline__ void ldsm4(uint32_t* r, uint32_t addr) {
    asm volatile("ldmatrix.sync.aligned.m8n8.x4.shared.b16 {%0,%1,%2,%3}, [%4];\n"
                 : "=r"(r[0]), "=r"(r[1]), "=r"(r[2]), "=r"(r[3])
                 : "r"(addr));
}
// SW64 swizzle for 64-byte rows (GEMM tiles)
__device__ __forceinline__ uint32_t swz(uint32_t off) {
    return off ^ ((off >> 3) & 0x30);
}

// ---------------- dense input conversion ----------------
__global__ void conv_dense_kernel(const float* __restrict__ d,
                                  uint16_t* __restrict__ hi, uint16_t* __restrict__ lo) {
    int idx = blockIdx.x * blockDim.x + threadIdx.x;   // BATCH*32
    int b = idx >> 5, k = idx & 31;
    float v = (k < 13) ? d[b * 13 + k] : 0.f;
    uint16_t h, l;
    f2hilo(v, h, l);
    hi[idx] = h; lo[idx] = l;
}

// ---------------- weight transpose + hi/lo split (coalesced via smem tile) ----
__global__ void conv_wt_t_kernel(const float* __restrict__ W,
                                 uint16_t* __restrict__ hi, uint16_t* __restrict__ lo,
                                 int K, int N, int Kpad) {
    __shared__ float tile[32][65];
    const int tx = threadIdx.x & 31;
    const int ty = threadIdx.x >> 5;
    const int n0 = blockIdx.x * 32;
    const int k0 = blockIdx.y * 64;

#pragma unroll
    for (int kk = ty; kk < 64; kk += 8) {
        int k = k0 + kk, n = n0 + tx;
        tile[tx][kk] = (k < K) ? W[(size_t)k * N + n] : 0.f;
    }
    __syncthreads();

#pragma unroll
    for (int r = ty; r < 32; r += 8) {
        int n = n0 + r;
        int k = k0 + tx * 2;
        if (k < Kpad) {
            float v0 = tile[r][tx * 2], v1 = tile[r][tx * 2 + 1];
            uint16_t h0, l0, h1, l1;
            f2hilo(v0, h0, l0);
            f2hilo(v1, h1, l1);
            *(uint32_t*)&hi[(size_t)n * Kpad + k] = (uint32_t)h0 | ((uint32_t)h1 << 16);
            *(uint32_t*)&lo[(size_t)n * Kpad + k] = (uint32_t)l0 | ((uint32_t)l1 << 16);
        }
    }
}

// ---------------- bf16x3 GEMM (R10/R12 config: 128x128, 2 CTA/SM, 3-stage) ----
#define STAGE_B 32768          // Ah 8K | Al 8K | Bh 8K | Bl 8K
#define SOFF_AL 8192
#define SOFF_BH 16384
#define SOFF_BL 24576

__global__ __launch_bounds__(256, 2)
void gemm_hmma(const uint16_t* __restrict__ Ahi, const uint16_t* __restrict__ Alo,
               const uint16_t* __restrict__ Whi, const uint16_t* __restrict__ Wlo,
               const float* __restrict__ bias,
               uint16_t* __restrict__ Ohi, uint16_t* __restrict__ Olo,
               int Nsz, int K, int relu) {
    extern __shared__ __align__(16) uint8_t dsm[];
    const uint32_t sbase = smem_u32(dsm);

    const int tid  = threadIdx.x;
    const int lane = tid & 31;
    const int warp = tid >> 5;
    const int wm = warp & 3;
    const int wn = warp >> 2;
    const size_t mBase = (size_t)blockIdx.y * 128;
    const int    nBase = blockIdx.x * 128;
    const int    nch   = K >> 5;

    const int r0 = tid >> 2, ch = tid & 3;
    const uint16_t* gp[4];
    gp[0] = Ahi + (mBase + r0) * (size_t)K + ch * 8;
    gp[1] = Alo + (mBase + r0) * (size_t)K + ch * 8;
    gp[2] = Whi + (size_t)(nBase + r0) * K + ch * 8;
    gp[3] = Wlo + (size_t)(nBase + r0) * K + ch * 8;
    const uint32_t soff = swz((uint32_t)r0 * 64 + ch * 16);
    const size_t rowD = (size_t)64 * K;

    auto issue = [&](int c) {
        const uint32_t st = sbase + (c % 3) * STAGE_B + soff;
        const int k0 = c << 5;
#pragma unroll
        for (int rg = 0; rg < 4; rg++) {
            cp16(st + rg * 8192,        gp[rg] + k0);
            cp16(st + rg * 8192 + 4096, gp[rg] + rowD + k0);
        }
    };

    float acc[2][8][4];
#pragma unroll
    for (int a = 0; a < 2; a++)
#pragma unroll
        for (int b = 0; b < 8; b++)
#pragma unroll
            for (int c = 0; c < 4; c++) acc[a][b][c] = 0.f;

    const uint32_t aRow = (uint32_t)(wm * 32 + (lane & 15)) * 64 + (lane >> 4) * 16;
    const uint32_t bRow = (uint32_t)(wn * 64 + (lane & 7) + ((lane >> 4) << 3)) * 64
                        + (((lane >> 3) & 1) << 4);

    issue(0); CP_COMMIT();
    if (nch > 1) { issue(1); CP_COMMIT(); }

    for (int c = 0; c < nch; c++) {
        if (c + 1 < nch) CP_WAIT1(); else CP_WAIT0();
        __syncthreads();
        if (c + 2 < nch) { issue(c + 2); CP_COMMIT(); }

        const uint32_t st = sbase + (c % 3) * STAGE_B;
#pragma unroll
        for (int kk = 0; kk < 2; kk++) {
            uint32_t aH[2][4], aL[2][4], bB[4][4];
#pragma unroll
            for (int mt = 0; mt < 2; mt++) {
                uint32_t off = swz(aRow + mt * 16 * 64 + kk * 32);
                ldsm4(aH[mt], st + off);
                ldsm4(aL[mt], st + SOFF_AL + off);
            }
#pragma unroll
            for (int np = 0; np < 4; np++)
                ldsm4(bB[np], st + SOFF_BH + swz(bRow + np * 16 * 64 + kk * 32));

#pragma unroll
            for (int np = 0; np < 4; np++)
#pragma unroll
                for (int mt = 0; mt < 2; mt++) {
                    mma_bf16(acc[mt][np * 2],     aH[mt], &bB[np][0]);
                    mma_bf16(acc[mt][np * 2 + 1], aH[mt], &bB[np][2]);
                }
#pragma unroll
            for (int np = 0; np < 4; np++) {
#pragma unroll
                for (int mt = 0; mt < 2; mt++) {
                    mma_bf16(acc[mt][np * 2],     aL[mt], &bB[np][0]);
                    mma_bf16(acc[mt][np * 2 + 1], aL[mt], &bB[np][2]);
                }
                ldsm4(bB[np], st + SOFF_BL + swz(bRow + np * 16 * 64 + kk * 32));
            }
#pragma unroll
            for (int np = 0; np < 4; np++)
#pragma unroll
                for (int mt = 0; mt < 2; mt++) {
                    mma_bf16(acc[mt][np * 2],     aH[mt], &bB[np][0]);
                    mma_bf16(acc[mt][np * 2 + 1], aH[mt], &bB[np][2]);
                }
        }
    }

#pragma unroll
    for (int mt = 0; mt < 2; mt++) {
        size_t m0 = mBase + wm * 32 + mt * 16 + (lane >> 2);
#pragma unroll
        for (int nt = 0; nt < 8; nt++) {
            int n = nBase + wn * 64 + nt * 8 + (lane & 3) * 2;
            float b0 = bias[n], b1 = bias[n + 1];
            float v0 = acc[mt][nt][0] + b0;
            float v1 = acc[mt][nt][1] + b1;
            float v2 = acc[mt][nt][2] + b0;
            float v3 = acc[mt][nt][3] + b1;
            if (relu) {
                v0 = fmaxf(v0, 0.f); v1 = fmaxf(v1, 0.f);
                v2 = fmaxf(v2, 0.f); v3 = fmaxf(v3, 0.f);
            }
            uint16_t h0, l0, h1, l1;
            f2hilo(v0, h0, l0); f2hilo(v1, h1, l1);
            *(uint32_t*)&Ohi[m0 * Nsz + n] = (uint32_t)h0 | ((uint32_t)h1 << 16);
            *(uint32_t*)&Olo[m0 * Nsz + n] = (uint32_t)l0 | ((uint32_t)l1 << 16);
            f2hilo(v2, h0, l0); f2hilo(v3, h1, l1);
            *(uint32_t*)&Ohi[(m0 + 8) * Nsz + n] = (uint32_t)h0 | ((uint32_t)h1 << 16);
            *(uint32_t*)&Olo[(m0 + 8) * Nsz + n] = (uint32_t)l0 | ((uint32_t)l1 << 16);
        }
    }
}

// ---------------- interaction via HMMA gram, k-split halves, 2 CTA/SM --------
// Per sample per half: 32 rows x 64 k bf16, row stride 144B (144 mod 128 = 16
// -> bank-walking, conflict-free ldmatrix), hi plane then lo plane.
// smem/sample = 2*32*144 = 9216 B; 8 samples/block = 73728 B -> 2 CTAs/SM.
#define HSTRIDE 144
#define HPLANE  4608          // 32 * 144
#define HSAMP   9216          // 2 planes

__global__ __launch_bounds__(256, 2)
void interact_kernel(const uint16_t* __restrict__ Hhi, const uint16_t* __restrict__ Hlo,
                     const float* __restrict__ emb, const int* __restrict__ sidx,
                     uint16_t* __restrict__ Ohi, uint16_t* __restrict__ Olo) {
    extern __shared__ __align__(16) uint8_t ism[];
    const int warp = threadIdx.x >> 5;
    const int lane = threadIdx.x & 31;
    const size_t s = (size_t)blockIdx.x * 8 + warp;
    uint8_t* my = ism + warp * HSAMP;
    const uint32_t base = smem_u32(my);

    int idx26[26];
#pragma unroll
    for (int v = 0; v < 26; v++) idx26[v] = sidx[s * 26 + v] & (VOCAB - 1);

    // copy h through to output cols [0,128)
    {
        uint2 hh = *(const uint2*)&Hhi[s * 128 + lane * 4];
        uint2 ll = *(const uint2*)&Hlo[s * 128 + lane * 4];
        *(uint2*)&Ohi[s * 512 + lane * 4] = hh;
        *(uint2*)&Olo[s * 512 + lane * 4] = ll;
    }

    float acc[2][4][4];
#pragma unroll
    for (int a = 0; a < 2; a++)
#pragma unroll
        for (int b = 0; b < 4; b++)
#pragma unroll
            for (int c = 0; c < 4; c++) acc[a][b][c] = 0.f;

    const uint32_t aoff = base + (uint32_t)(lane & 15) * HSTRIDE + (lane >> 4) * 16;
    const uint32_t boff = base + (uint32_t)((lane & 7) + ((lane >> 4) << 3)) * HSTRIDE
                        + (((lane >> 3) & 1) << 4);

#pragma unroll
    for (int ph = 0; ph < 2; ph++) {
        const int kb0 = ph * 64;      // k-column base of this half

        // row 0 = h: one u32 (2 bf16) per lane per plane
        *(uint32_t*)(my + lane * 4) =
            *(const uint32_t*)&Hhi[s * 128 + kb0 + lane * 2];
        *(uint32_t*)(my + HPLANE + lane * 4) =
            *(const uint32_t*)&Hlo[s * 128 + kb0 + lane * 2];
        // zero pad rows 27..31
#pragma unroll
        for (int r = 27; r < 32; r++) {
            *(uint32_t*)(my + r * HSTRIDE + lane * 4) = 0u;
            *(uint32_t*)(my + HPLANE + r * HSTRIDE + lane * 4) = 0u;
        }

        // gather rows 1..26 in waves of 8 (float2 = this half's 2 k-vals/lane)
#pragma unroll
        for (int w0 = 0; w0 < 26; w0 += 8) {
            float2 e[8];
            const int cnt = (26 - w0 < 8) ? (26 - w0) : 8;
#pragma unroll
            for (int j = 0; j < 8; j++)
                if (j < cnt)
                    e[j] = *(const float2*)&emb[(size_t)idx26[w0 + j] * 128 + kb0 + lane * 2];
#pragma unroll
            for (int j = 0; j < 8; j++)
                if (j < cnt) {
                    const int r = w0 + j + 1;
                    uint16_t h0, l0, h1, l1;
                    f2hilo(e[j].x, h0, l0);
                    f2hilo(e[j].y, h1, l1);
                    *(uint32_t*)(my + r * HSTRIDE + lane * 4) =
                        (uint32_t)h0 | ((uint32_t)h1 << 16);
                    *(uint32_t*)(my + HPLANE + r * HSTRIDE + lane * 4) =
                        (uint32_t)l0 | ((uint32_t)l1 << 16);
                }
        }
        __syncwarp();

        // gram accumulate over this half's 4 k16-steps (bf16x3 passes)
#pragma unroll
        for (int ks = 0; ks < 4; ks++) {
            const uint32_t kb = ks * 32;
            uint32_t aH[2][4], aL[2][4], bB[2][4];
            ldsm4(aH[0], aoff + kb);
            ldsm4(aH[1], aoff + 16 * HSTRIDE + kb);
            ldsm4(aL[0], aoff + HPLANE + kb);
            ldsm4(aL[1], aoff + HPLANE + 16 * HSTRIDE + kb);
            ldsm4(bB[0], boff + kb);
            ldsm4(bB[1], boff + 16 * HSTRIDE + kb);
#pragma unroll
            for (int g = 0; g < 2; g++)
#pragma unroll
                for (int mt = 0; mt < 2; mt++) {
                    mma_bf16(acc[mt][g * 2],     aH[mt], &bB[g][0]);
                    mma_bf16(acc[mt][g * 2 + 1], aH[mt], &bB[g][2]);
                }
#pragma unroll
            for (int g = 0; g < 2; g++) {
#pragma unroll
                for (int mt = 0; mt < 2; mt++) {
                    mma_bf16(acc[mt][g * 2],     aL[mt], &bB[g][0]);
                    mma_bf16(acc[mt][g * 2 + 1], aL[mt], &bB[g][2]);
                }
                ldsm4(bB[g], boff + HPLANE + g * 16 * HSTRIDE + kb);
            }
#pragma unroll
            for (int g = 0; g < 2; g++)
#pragma unroll
                for (int mt = 0; mt < 2; mt++) {
                    mma_bf16(acc[mt][g * 2],     aH[mt], &bB[g][0]);
                    mma_bf16(acc[mt][g * 2 + 1], aH[mt], &bB[g][2]);
                }
        }
        __syncwarp();   // half's smem fully consumed before overwrite
    }

    // epilogue: store triu(27) entries -> cols [128, 506)
#pragma unroll
    for (int mt = 0; mt < 2; mt++)
#pragma unroll
        for (int nt = 0; nt < 4; nt++)
#pragma unroll
            for (int q = 0; q < 4; q++) {
                int i = mt * 16 + (lane >> 2) + ((q >> 1) << 3);
                int j = nt * 8 + (lane & 3) * 2 + (q & 1);
                if (i <= j && j < 27) {
                    int flat = 27 * i - (i * (i - 1)) / 2 + (j - i);
                    uint16_t h, l;
                    f2hilo(acc[mt][nt][q], h, l);
                    Ohi[s * 512 + 128 + flat] = h;
                    Olo[s * 512 + 128 + flat] = l;
                }
            }
    // zero pad cols [506, 512)
    if (lane < 6) {
        Ohi[s * 512 + 506 + lane] = 0;
        Olo[s * 512 + 506 + lane] = 0;
    }
}

// ---------------- final 256 -> 1 dot ----------------
__global__ void final_dot_kernel(const uint16_t* __restrict__ Ahi, const uint16_t* __restrict__ Alo,
                                 const float* __restrict__ w, const float* __restrict__ b,
                                 float* __restrict__ out) {
    const int warp = threadIdx.x >> 5;
    const int lane = threadIdx.x & 31;
    const size_t s = (size_t)blockIdx.x * 8 + warp;
    uint4 h4 = *(const uint4*)&Ahi[s * 256 + lane * 8];
    uint4 l4 = *(const uint4*)&Alo[s * 256 + lane * 8];
    uint32_t hw[4] = {h4.x, h4.y, h4.z, h4.w};
    uint32_t lw[4] = {l4.x, l4.y, l4.z, l4.w};
    float acc = 0.f;
#pragma unroll
    for (int q = 0; q < 4; q++) {
        float v0 = b2f((uint16_t)(hw[q] & 0xFFFF)) + b2f((uint16_t)(lw[q] & 0xFFFF));
        float v1 = b2f((uint16_t)(hw[q] >> 16))    + b2f((uint16_t)(lw[q] >> 16));
        acc += v0 * w[lane * 8 + q * 2];
        acc += v1 * w[lane * 8 + q * 2 + 1];
    }
#pragma unroll
    for (int o = 16; o; o >>= 1) acc += __shfl_xor_sync(0xFFFFFFFFu, acc, o);
    if (lane == 0) out[s] = acc + b[0];
}

// ---------------- host launch ----------------
extern "C" void kernel_launch(void* const* d_in, const int* in_sizes, int n_in,
                              void* d_out, int out_size) {
    const float* dense = (const float*)d_in[0];
    const int*   sidx  = (const int*)d_in[1];
    const float* emb   = (const float*)d_in[2];
    const float* bw0 = (const float*)d_in[3];  const float* bb0 = (const float*)d_in[4];
    const float* bw1 = (const float*)d_in[5];  const float* bb1 = (const float*)d_in[6];
    const float* bw2 = (const float*)d_in[7];  const float* bb2 = (const float*)d_in[8];
    const float* tw0 = (const float*)d_in[9];  const float* tb0 = (const float*)d_in[10];
    const float* tw1 = (const float*)d_in[11]; const float* tb1 = (const float*)d_in[12];
    const float* tw2 = (const float*)d_in[13]; const float* tb2 = (const float*)d_in[14];
    const float* tw3 = (const float*)d_in[15]; const float* tb3 = (const float*)d_in[16];
    const float* tw4 = (const float*)d_in[17]; const float* tb4 = (const float*)d_in[18];

    uint16_t *bufAh, *bufAl, *bufBh, *bufBl, *wth, *wtl;
    cudaGetSymbolAddress((void**)&bufAh, g_bufA_hi);
    cudaGetSymbolAddress((void**)&bufAl, g_bufA_lo);
    cudaGetSymbolAddress((void**)&bufBh, g_bufB_hi);
    cudaGetSymbolAddress((void**)&bufBl, g_bufB_lo);
    cudaGetSymbolAddress((void**)&wth, g_wt_hi);
    cudaGetSymbolAddress((void**)&wtl, g_wt_lo);

    const int DSM = 3 * STAGE_B;       // 98304
    const int ISM = 8 * HSAMP;         // 73728
    cudaFuncSetAttribute(gemm_hmma, cudaFuncAttributeMaxDynamicSharedMemorySize, DSM);
    cudaFuncSetAttribute(interact_kernel, cudaFuncAttributeMaxDynamicSharedMemorySize, ISM);

    dim3 blk(256);

    // conversions
    conv_dense_kernel<<<BATCH * 32 / 256, blk>>>(dense, bufAh, bufAl);
    conv_wt_t_kernel<<<dim3(512 / 32, 1),   blk>>>(bw0, wth + OFF_BW0, wtl + OFF_BW0, 13,   512,  32);
    conv_wt_t_kernel<<<dim3(256 / 32, 8),   blk>>>(bw1, wth + OFF_BW1, wtl + OFF_BW1, 512,  256,  512);
    conv_wt_t_kernel<<<dim3(128 / 32, 4),   blk>>>(bw2, wth + OFF_BW2, wtl + OFF_BW2, 256,  128,  256);
    conv_wt_t_kernel<<<dim3(1024 / 32, 8),  blk>>>(tw0, wth + OFF_TW0, wtl + OFF_TW0, 506,  1024, 512);
    conv_wt_t_kernel<<<dim3(1024 / 32, 16), blk>>>(tw1, wth + OFF_TW1, wtl + OFF_TW1, 1024, 1024, 1024);
    conv_wt_t_kernel<<<dim3(512 / 32, 16),  blk>>>(tw2, wth + OFF_TW2, wtl + OFF_TW2, 1024, 512,  1024);
    conv_wt_t_kernel<<<dim3(256 / 32, 8),   blk>>>(tw3, wth + OFF_TW3, wtl + OFF_TW3, 512,  256,  512);

    // bottom MLP
    gemm_hmma<<<dim3(4, 512), blk, DSM>>>(bufAh, bufAl, wth + OFF_BW0, wtl + OFF_BW0, bb0, bufBh, bufBl, 512, 32, 1);
    gemm_hmma<<<dim3(2, 512), blk, DSM>>>(bufBh, bufBl, wth + OFF_BW1, wtl + OFF_BW1, bb1, bufAh, bufAl, 256, 512, 1);
    gemm_hmma<<<dim3(1, 512), blk, DSM>>>(bufAh, bufAl, wth + OFF_BW2, wtl + OFF_BW2, bb2, bufBh, bufBl, 128, 256, 1);

    // gather + interaction (HMMA gram, k-split, 2 CTA/SM) -> [B, 512]
    interact_kernel<<<BATCH / 8, blk, ISM>>>(bufBh, bufBl, emb, sidx, bufAh, bufAl);

    // top MLP
    gemm_hmma<<<dim3(8, 512), blk, DSM>>>(bufAh, bufAl, wth + OFF_TW0, wtl + OFF_TW0, tb0, bufBh, bufBl, 1024, 512, 1);
    gemm_hmma<<<dim3(8, 512), blk, DSM>>>(bufBh, bufBl, wth + OFF_TW1, wtl + OFF_TW1, tb1, bufAh, bufAl, 1024, 1024, 1);
    gemm_hmma<<<dim3(4, 512), blk, DSM>>>(bufAh, bufAl, wth + OFF_TW2, wtl + OFF_TW2, tb2, bufBh, bufBl, 512, 1024, 1);
    gemm_hmma<<<dim3(2, 512), blk, DSM>>>(bufBh, bufBl, wth + OFF_TW3, wtl + OFF_TW3, tb3, bufAh, bufAl, 256, 512, 1);

    // final 256 -> 1
    final_dot_kernel<<<BATCH / 8, blk>>>(bufAh, bufAl, tw4, tb4, (float*)d_out);
}

// round 16
// speedup vs baseline: 2.6701x; 1.5216x over previous
#include <cuda_runtime.h>
#include <cuda_bf16.h>
#include <stdint.h>

#define BATCH 65536
#define VOCAB 1048576

// ---------------- device scratch (no allocation allowed) ----------------
__device__ uint16_t g_bufA_hi[BATCH * 1024];
__device__ uint16_t g_bufA_lo[BATCH * 1024];
__device__ uint16_t g_bufB_hi[BATCH * 1024];
__device__ uint16_t g_bufB_lo[BATCH * 1024];
__device__ uint16_t g_wt_hi[2408448];
__device__ uint16_t g_wt_lo[2408448];
__device__ float    g_fin[BATCH * 256];

// weight offsets (transposed [N,K], K padded to mult of 32):
#define OFF_BW0 0        // [512 ,  32]
#define OFF_BW1 16384    // [256 , 512]
#define OFF_BW2 147456   // [128 , 256]
#define OFF_TW0 180224   // [1024, 512]
#define OFF_TW1 704512   // [1024,1024]
#define OFF_TW2 1753088  // [512 ,1024]
#define OFF_TW3 2277376  // [256 , 512]   total 2408448

__device__ __forceinline__ void f2hilo(float x, uint16_t &hi, uint16_t &lo) {
    __nv_bfloat16 h = __float2bfloat16(x);
    float hf = __bfloat162float(h);
    __nv_bfloat16 l = __float2bfloat16(x - hf);
    hi = __bfloat16_as_ushort(h);
    lo = __bfloat16_as_ushort(l);
}
__device__ __forceinline__ float b2f(uint16_t u) {
    return __bfloat162float(__ushort_as_bfloat16(u));
}

// ---------------- PTX helpers ----------------
__device__ __forceinline__ uint32_t smem_u32(const void* p) {
    return (uint32_t)__cvta_generic_to_shared(p);
}
__device__ __forceinline__ void cp16(uint32_t s, const void* g) {
    asm volatile("cp.async.cg.shared.global [%0], [%1], 16;\n" :: "r"(s), "l"(g));
}
#define CP_COMMIT() asm volatile("cp.async.commit_group;\n" ::: "memory")
#define CP_WAIT0()  asm volatile("cp.async.wait_group 0;\n" ::: "memory")
#define CP_WAIT1()  asm volatile("cp.async.wait_group 1;\n" ::: "memory")

__device__ __forceinline__ void mma_bf16(float* c, const uint32_t* a, const uint32_t* b) {
    asm volatile(
        "mma.sync.aligned.m16n8k16.row.col.f32.bf16.bf16.f32 "
        "{%0,%1,%2,%3}, {%4,%5,%6,%7}, {%8,%9}, {%0,%1,%2,%3};\n"
        : "+f"(c[0]), "+f"(c[1]), "+f"(c[2]), "+f"(c[3])
        : "r"(a[0]), "r"(a[1]), "r"(a[2]), "r"(a[3]), "r"(b[0]), "r"(b[1]));
}
__device__ __forceinline__ void ldsm4(uint32_t* r, uint32_t addr) {
    asm volatile("ldmatrix.sync.aligned.m8n8.x4.shared.b16 {%0,%1,%2,%3}, [%4];\n"
                 : "=r"(r[0]), "=r"(r[1]), "=r"(r[2]), "=r"(r[3])
                 : "r"(addr));
}
// SW64 swizzle for 64-byte rows (GEMM tiles)
__device__ __forceinline__ uint32_t swz(uint32_t off) {
    return off ^ ((off >> 3) & 0x30);
}

// ---------------- dense input conversion ----------------
__global__ void conv_dense_kernel(const float* __restrict__ d,
                                  uint16_t* __restrict__ hi, uint16_t* __restrict__ lo) {
    int idx = blockIdx.x * blockDim.x + threadIdx.x;   // BATCH*32
    int b = idx >> 5, k = idx & 31;
    float v = (k < 13) ? d[b * 13 + k] : 0.f;
    uint16_t h, l;
    f2hilo(v, h, l);
    hi[idx] = h; lo[idx] = l;
}

// ---------------- weight transpose + hi/lo split (coalesced via smem tile) ----
__global__ void conv_wt_t_kernel(const float* __restrict__ W,
                                 uint16_t* __restrict__ hi, uint16_t* __restrict__ lo,
                                 int K, int N, int Kpad) {
    __shared__ float tile[32][65];
    const int tx = threadIdx.x & 31;
    const int ty = threadIdx.x >> 5;
    const int n0 = blockIdx.x * 32;
    const int k0 = blockIdx.y * 64;

#pragma unroll
    for (int kk = ty; kk < 64; kk += 8) {
        int k = k0 + kk, n = n0 + tx;
        tile[tx][kk] = (k < K) ? W[(size_t)k * N + n] : 0.f;
    }
    __syncthreads();

#pragma unroll
    for (int r = ty; r < 32; r += 8) {
        int n = n0 + r;
        int k = k0 + tx * 2;
        if (k < Kpad) {
            float v0 = tile[r][tx * 2], v1 = tile[r][tx * 2 + 1];
            uint16_t h0, l0, h1, l1;
            f2hilo(v0, h0, l0);
            f2hilo(v1, h1, l1);
            *(uint32_t*)&hi[(size_t)n * Kpad + k] = (uint32_t)h0 | ((uint32_t)h1 << 16);
            *(uint32_t*)&lo[(size_t)n * Kpad + k] = (uint32_t)l0 | ((uint32_t)l1 << 16);
        }
    }
}

// ---------------- bf16x3 GEMM (R12 config: 128x128, 2 CTA/SM, 3-stage) -------
// mode 0: bf16 hi/lo planes out.  mode 1: fp32 out (Ofp).
#define STAGE_B 32768          // Ah 8K | Al 8K | Bh 8K | Bl 8K
#define SOFF_AL 8192
#define SOFF_BH 16384
#define SOFF_BL 24576

__global__ __launch_bounds__(256, 2)
void gemm_hmma(const uint16_t* __restrict__ Ahi, const uint16_t* __restrict__ Alo,
               const uint16_t* __restrict__ Whi, const uint16_t* __restrict__ Wlo,
               const float* __restrict__ bias,
               uint16_t* __restrict__ Ohi, uint16_t* __restrict__ Olo,
               float* __restrict__ Ofp,
               int Nsz, int K, int relu, int mode) {
    extern __shared__ __align__(16) uint8_t dsm[];
    const uint32_t sbase = smem_u32(dsm);

    const int tid  = threadIdx.x;
    const int lane = tid & 31;
    const int warp = tid >> 5;
    const int wm = warp & 3;
    const int wn = warp >> 2;
    const size_t mBase = (size_t)blockIdx.y * 128;
    const int    nBase = blockIdx.x * 128;
    const int    nch   = K >> 5;

    const int r0 = tid >> 2, ch = tid & 3;
    const uint16_t* gp[4];
    gp[0] = Ahi + (mBase + r0) * (size_t)K + ch * 8;
    gp[1] = Alo + (mBase + r0) * (size_t)K + ch * 8;
    gp[2] = Whi + (size_t)(nBase + r0) * K + ch * 8;
    gp[3] = Wlo + (size_t)(nBase + r0) * K + ch * 8;
    const uint32_t soff = swz((uint32_t)r0 * 64 + ch * 16);
    const size_t rowD = (size_t)64 * K;

    auto issue = [&](int c) {
        const uint32_t st = sbase + (c % 3) * STAGE_B + soff;
        const int k0 = c << 5;
#pragma unroll
        for (int rg = 0; rg < 4; rg++) {
            cp16(st + rg * 8192,        gp[rg] + k0);
            cp16(st + rg * 8192 + 4096, gp[rg] + rowD + k0);
        }
    };

    float acc[2][8][4];
#pragma unroll
    for (int a = 0; a < 2; a++)
#pragma unroll
        for (int b = 0; b < 8; b++)
#pragma unroll
            for (int c = 0; c < 4; c++) acc[a][b][c] = 0.f;

    const uint32_t aRow = (uint32_t)(wm * 32 + (lane & 15)) * 64 + (lane >> 4) * 16;
    const uint32_t bRow = (uint32_t)(wn * 64 + (lane & 7) + ((lane >> 4) << 3)) * 64
                        + (((lane >> 3) & 1) << 4);

    issue(0); CP_COMMIT();
    if (nch > 1) { issue(1); CP_COMMIT(); }

    for (int c = 0; c < nch; c++) {
        if (c + 1 < nch) CP_WAIT1(); else CP_WAIT0();
        __syncthreads();
        if (c + 2 < nch) { issue(c + 2); CP_COMMIT(); }

        const uint32_t st = sbase + (c % 3) * STAGE_B;
#pragma unroll
        for (int kk = 0; kk < 2; kk++) {
            uint32_t aH[2][4], aL[2][4], bB[4][4];
#pragma unroll
            for (int mt = 0; mt < 2; mt++) {
                uint32_t off = swz(aRow + mt * 16 * 64 + kk * 32);
                ldsm4(aH[mt], st + off);
                ldsm4(aL[mt], st + SOFF_AL + off);
            }
#pragma unroll
            for (int np = 0; np < 4; np++)
                ldsm4(bB[np], st + SOFF_BH + swz(bRow + np * 16 * 64 + kk * 32));

#pragma unroll
            for (int np = 0; np < 4; np++)
#pragma unroll
                for (int mt = 0; mt < 2; mt++) {
                    mma_bf16(acc[mt][np * 2],     aH[mt], &bB[np][0]);
                    mma_bf16(acc[mt][np * 2 + 1], aH[mt], &bB[np][2]);
                }
#pragma unroll
            for (int np = 0; np < 4; np++) {
#pragma unroll
                for (int mt = 0; mt < 2; mt++) {
                    mma_bf16(acc[mt][np * 2],     aL[mt], &bB[np][0]);
                    mma_bf16(acc[mt][np * 2 + 1], aL[mt], &bB[np][2]);
                }
                ldsm4(bB[np], st + SOFF_BL + swz(bRow + np * 16 * 64 + kk * 32));
            }
#pragma unroll
            for (int np = 0; np < 4; np++)
#pragma unroll
                for (int mt = 0; mt < 2; mt++) {
                    mma_bf16(acc[mt][np * 2],     aH[mt], &bB[np][0]);
                    mma_bf16(acc[mt][np * 2 + 1], aH[mt], &bB[np][2]);
                }
        }
    }

#pragma unroll
    for (int mt = 0; mt < 2; mt++) {
        size_t m0 = mBase + wm * 32 + mt * 16 + (lane >> 2);
#pragma unroll
        for (int nt = 0; nt < 8; nt++) {
            int n = nBase + wn * 64 + nt * 8 + (lane & 3) * 2;
            float b0 = bias[n], b1 = bias[n + 1];
            float v0 = acc[mt][nt][0] + b0;
            float v1 = acc[mt][nt][1] + b1;
            float v2 = acc[mt][nt][2] + b0;
            float v3 = acc[mt][nt][3] + b1;
            if (relu) {
                v0 = fmaxf(v0, 0.f); v1 = fmaxf(v1, 0.f);
                v2 = fmaxf(v2, 0.f); v3 = fmaxf(v3, 0.f);
            }
            if (mode) {
                *(float2*)&Ofp[m0 * Nsz + n]       = make_float2(v0, v1);
                *(float2*)&Ofp[(m0 + 8) * Nsz + n] = make_float2(v2, v3);
            } else {
                uint16_t h0, l0, h1, l1;
                f2hilo(v0, h0, l0); f2hilo(v1, h1, l1);
                *(uint32_t*)&Ohi[m0 * Nsz + n] = (uint32_t)h0 | ((uint32_t)h1 << 16);
                *(uint32_t*)&Olo[m0 * Nsz + n] = (uint32_t)l0 | ((uint32_t)l1 << 16);
                f2hilo(v2, h0, l0); f2hilo(v3, h1, l1);
                *(uint32_t*)&Ohi[(m0 + 8) * Nsz + n] = (uint32_t)h0 | ((uint32_t)h1 << 16);
                *(uint32_t*)&Olo[(m0 + 8) * Nsz + n] = (uint32_t)l0 | ((uint32_t)l1 << 16);
            }
        }
    }
}

// ---------------- interaction via HMMA gram (bf16x3), 1 warp/sample ----------
// R12 per-warp code verbatim; block shrunk to 128 threads (4 samples) so
// 3 CTAs/SM fit (3 x 69632 B = 208 KB smem) -> 12 warps/SM gathering.
#define ISTRIDE 272
#define IPLANE  8704          // 32 * 272
#define ISAMP   17408         // 2 planes

__global__ __launch_bounds__(128, 3)
void interact_kernel(const uint16_t* __restrict__ Hhi, const uint16_t* __restrict__ Hlo,
                     const float* __restrict__ emb, const int* __restrict__ sidx,
                     uint16_t* __restrict__ Ohi, uint16_t* __restrict__ Olo) {
    extern __shared__ __align__(16) uint8_t ism[];
    const int warp = threadIdx.x >> 5;
    const int lane = threadIdx.x & 31;
    const size_t s = (size_t)blockIdx.x * 4 + warp;
    uint8_t* my = ism + warp * ISAMP;
    const uint32_t base = smem_u32(my);

    int idx26[26];
#pragma unroll
    for (int v = 0; v < 26; v++) idx26[v] = sidx[s * 26 + v] & (VOCAB - 1);

    // row 0 = h (bf16 hi/lo pairs); also copy to output cols [0,128)
    {
        uint2 hh = *(const uint2*)&Hhi[s * 128 + lane * 4];
        uint2 ll = *(const uint2*)&Hlo[s * 128 + lane * 4];
        *(uint2*)(my + lane * 8) = hh;
        *(uint2*)(my + IPLANE + lane * 8) = ll;
        *(uint2*)&Ohi[s * 512 + lane * 4] = hh;
        *(uint2*)&Olo[s * 512 + lane * 4] = ll;
    }
    // zero pad rows 27..31 (both planes)
#pragma unroll
    for (int r = 27; r < 32; r++) {
        *(uint2*)(my + r * ISTRIDE + lane * 8) = make_uint2(0, 0);
        *(uint2*)(my + IPLANE + r * ISTRIDE + lane * 8) = make_uint2(0, 0);
    }

    // gather rows 1..26 in waves of 8 (MLP=8), split fp32 -> bf16 hi/lo
#pragma unroll
    for (int w0 = 0; w0 < 26; w0 += 8) {
        float4 e[8];
        const int cnt = (26 - w0 < 8) ? (26 - w0) : 8;
#pragma unroll
        for (int j = 0; j < 8; j++)
            if (j < cnt)
                e[j] = *(const float4*)&emb[(size_t)idx26[w0 + j] * 128 + lane * 4];
#pragma unroll
        for (int j = 0; j < 8; j++)
            if (j < cnt) {
                const int r = w0 + j + 1;
                float f[4] = {e[j].x, e[j].y, e[j].z, e[j].w};
                uint16_t h[4], l[4];
#pragma unroll
                for (int q = 0; q < 4; q++) f2hilo(f[q], h[q], l[q]);
                *(uint2*)(my + r * ISTRIDE + lane * 8) =
                    make_uint2((uint32_t)h[0] | ((uint32_t)h[1] << 16),
                               (uint32_t)h[2] | ((uint32_t)h[3] << 16));
                *(uint2*)(my + IPLANE + r * ISTRIDE + lane * 8) =
                    make_uint2((uint32_t)l[0] | ((uint32_t)l[1] << 16),
                               (uint32_t)l[2] | ((uint32_t)l[3] << 16));
            }
    }
    __syncwarp();

    float acc[2][4][4];
#pragma unroll
    for (int a = 0; a < 2; a++)
#pragma unroll
        for (int b = 0; b < 4; b++)
#pragma unroll
            for (int c = 0; c < 4; c++) acc[a][b][c] = 0.f;

    const uint32_t aoff = base + (uint32_t)(lane & 15) * ISTRIDE + (lane >> 4) * 16;
    const uint32_t boff = base + (uint32_t)((lane & 7) + ((lane >> 4) << 3)) * ISTRIDE
                        + (((lane >> 3) & 1) << 4);

#pragma unroll
    for (int ks = 0; ks < 8; ks++) {
        const uint32_t kb = ks * 32;
        uint32_t aH[2][4], aL[2][4], bB[2][4];
        ldsm4(aH[0], aoff + kb);
        ldsm4(aH[1], aoff + 16 * ISTRIDE + kb);
        ldsm4(aL[0], aoff + IPLANE + kb);
        ldsm4(aL[1], aoff + IPLANE + 16 * ISTRIDE + kb);
        ldsm4(bB[0], boff + kb);
        ldsm4(bB[1], boff + 16 * ISTRIDE + kb);
#pragma unroll
        for (int g = 0; g < 2; g++)
#pragma unroll
            for (int mt = 0; mt < 2; mt++) {
                mma_bf16(acc[mt][g * 2],     aH[mt], &bB[g][0]);
                mma_bf16(acc[mt][g * 2 + 1], aH[mt], &bB[g][2]);
            }
#pragma unroll
        for (int g = 0; g < 2; g++) {
#pragma unroll
            for (int mt = 0; mt < 2; mt++) {
                mma_bf16(acc[mt][g * 2],     aL[mt], &bB[g][0]);
                mma_bf16(acc[mt][g * 2 + 1], aL[mt], &bB[g][2]);
            }
            ldsm4(bB[g], boff + IPLANE + g * 16 * ISTRIDE + kb);
        }
#pragma unroll
        for (int g = 0; g < 2; g++)
#pragma unroll
            for (int mt = 0; mt < 2; mt++) {
                mma_bf16(acc[mt][g * 2],     aH[mt], &bB[g][0]);
                mma_bf16(acc[mt][g * 2 + 1], aH[mt], &bB[g][2]);
            }
    }

    // epilogue: store triu(27) entries -> cols [128, 506)
#pragma unroll
    for (int mt = 0; mt < 2; mt++)
#pragma unroll
        for (int nt = 0; nt < 4; nt++)
#pragma unroll
            for (int q = 0; q < 4; q++) {
                int i = mt * 16 + (lane >> 2) + ((q >> 1) << 3);
                int j = nt * 8 + (lane & 3) * 2 + (q & 1);
                if (i <= j && j < 27) {
                    int flat = 27 * i - (i * (i - 1)) / 2 + (j - i);
                    uint16_t h, l;
                    f2hilo(acc[mt][nt][q], h, l);
                    Ohi[s * 512 + 128 + flat] = h;
                    Olo[s * 512 + 128 + flat] = l;
                }
            }
    // zero pad cols [506, 512)
    if (lane < 6) {
        Ohi[s * 512 + 506 + lane] = 0;
        Olo[s * 512 + 506 + lane] = 0;
    }
}

// ---------------- final 256 -> 1 dot (fp32 in) ----------------
__global__ void final_dot_kernel(const float* __restrict__ F, const float* __restrict__ w,
                                 const float* __restrict__ b, float* __restrict__ out) {
    const int warp = threadIdx.x >> 5;
    const int lane = threadIdx.x & 31;
    const size_t s = (size_t)blockIdx.x * 8 + warp;
    float acc = 0.f;
#pragma unroll
    for (int q = 0; q < 2; q++) {
        float4 x = *(const float4*)&F[s * 256 + lane * 8 + q * 4];
        acc += x.x * w[lane * 8 + q * 4]     + x.y * w[lane * 8 + q * 4 + 1]
             + x.z * w[lane * 8 + q * 4 + 2] + x.w * w[lane * 8 + q * 4 + 3];
    }
#pragma unroll
    for (int o = 16; o; o >>= 1) acc += __shfl_xor_sync(0xFFFFFFFFu, acc, o);
    if (lane == 0) out[s] = acc + b[0];
}

// ---------------- host launch ----------------
extern "C" void kernel_launch(void* const* d_in, const int* in_sizes, int n_in,
                              void* d_out, int out_size) {
    const float* dense = (const float*)d_in[0];
    const int*   sidx  = (const int*)d_in[1];
    const float* emb   = (const float*)d_in[2];
    const float* bw0 = (const float*)d_in[3];  const float* bb0 = (const float*)d_in[4];
    const float* bw1 = (const float*)d_in[5];  const float* bb1 = (const float*)d_in[6];
    const float* bw2 = (const float*)d_in[7];  const float* bb2 = (const float*)d_in[8];
    const float* tw0 = (const float*)d_in[9];  const float* tb0 = (const float*)d_in[10];
    const float* tw1 = (const float*)d_in[11]; const float* tb1 = (const float*)d_in[12];
    const float* tw2 = (const float*)d_in[13]; const float* tb2 = (const float*)d_in[14];
    const float* tw3 = (const float*)d_in[15]; const float* tb3 = (const float*)d_in[16];
    const float* tw4 = (const float*)d_in[17]; const float* tb4 = (const float*)d_in[18];

    uint16_t *bufAh, *bufAl, *bufBh, *bufBl, *wth, *wtl;
    float *fin;
    cudaGetSymbolAddress((void**)&bufAh, g_bufA_hi);
    cudaGetSymbolAddress((void**)&bufAl, g_bufA_lo);
    cudaGetSymbolAddress((void**)&bufBh, g_bufB_hi);
    cudaGetSymbolAddress((void**)&bufBl, g_bufB_lo);
    cudaGetSymbolAddress((void**)&wth, g_wt_hi);
    cudaGetSymbolAddress((void**)&wtl, g_wt_lo);
    cudaGetSymbolAddress((void**)&fin, g_fin);

    const int DSM = 3 * STAGE_B;       // 98304
    const int ISM = 4 * ISAMP;         // 69632
    cudaFuncSetAttribute(gemm_hmma, cudaFuncAttributeMaxDynamicSharedMemorySize, DSM);
    cudaFuncSetAttribute(interact_kernel, cudaFuncAttributeMaxDynamicSharedMemorySize, ISM);

    dim3 blk(256);
    dim3 iblk(128);

    // conversions
    conv_dense_kernel<<<BATCH * 32 / 256, blk>>>(dense, bufAh, bufAl);
    conv_wt_t_kernel<<<dim3(512 / 32, 1),   blk>>>(bw0, wth + OFF_BW0, wtl + OFF_BW0, 13,   512,  32);
    conv_wt_t_kernel<<<dim3(256 / 32, 8),   blk>>>(bw1, wth + OFF_BW1, wtl + OFF_BW1, 512,  256,  512);
    conv_wt_t_kernel<<<dim3(128 / 32, 4),   blk>>>(bw2, wth + OFF_BW2, wtl + OFF_BW2, 256,  128,  256);
    conv_wt_t_kernel<<<dim3(1024 / 32, 8),  blk>>>(tw0, wth + OFF_TW0, wtl + OFF_TW0, 506,  1024, 512);
    conv_wt_t_kernel<<<dim3(1024 / 32, 16), blk>>>(tw1, wth + OFF_TW1, wtl + OFF_TW1, 1024, 1024, 1024);
    conv_wt_t_kernel<<<dim3(512 / 32, 16),  blk>>>(tw2, wth + OFF_TW2, wtl + OFF_TW2, 1024, 512,  1024);
    conv_wt_t_kernel<<<dim3(256 / 32, 8),   blk>>>(tw3, wth + OFF_TW3, wtl + OFF_TW3, 512,  256,  512);

    // bottom MLP
    gemm_hmma<<<dim3(4, 512), blk, DSM>>>(bufAh, bufAl, wth + OFF_BW0, wtl + OFF_BW0, bb0, bufBh, bufBl, fin, 512, 32, 1, 0);
    gemm_hmma<<<dim3(2, 512), blk, DSM>>>(bufBh, bufBl, wth + OFF_BW1, wtl + OFF_BW1, bb1, bufAh, bufAl, fin, 256, 512, 1, 0);
    gemm_hmma<<<dim3(1, 512), blk, DSM>>>(bufAh, bufAl, wth + OFF_BW2, wtl + OFF_BW2, bb2, bufBh, bufBl, fin, 128, 256, 1, 0);

    // gather + interaction (HMMA gram, 3 CTAs/SM) -> [B, 512]
    interact_kernel<<<BATCH / 4, iblk, ISM>>>(bufBh, bufBl, emb, sidx, bufAh, bufAl);

    // top MLP
    gemm_hmma<<<dim3(8, 512), blk, DSM>>>(bufAh, bufAl, wth + OFF_TW0, wtl + OFF_TW0, tb0, bufBh, bufBl, fin, 1024, 512, 1, 0);
    gemm_hmma<<<dim3(8, 512), blk, DSM>>>(bufBh, bufBl, wth + OFF_TW1, wtl + OFF_TW1, tb1, bufAh, bufAl, fin, 1024, 1024, 1, 0);
    gemm_hmma<<<dim3(4, 512), blk, DSM>>>(bufAh, bufAl, wth + OFF_TW2, wtl + OFF_TW2, tb2, bufBh, bufBl, fin, 512, 1024, 1, 0);
    gemm_hmma<<<dim3(2, 512), blk, DSM>>>(bufBh, bufBl, wth + OFF_TW3, wtl + OFF_TW3, tb3, bufAh, bufAl, fin, 256, 512, 1, 1);

    // final 256 -> 1 (fp32 in)
    final_dot_kernel<<<BATCH / 8, blk>>>(fin, tw4, tb4, (float*)d_out);
}